// round 7
// baseline (speedup 1.0000x reference)
#include <cuda_runtime.h>
#include <math.h>

#define NN 4096
#define NPTS 32768

// scratch (static __device__, no allocation)
__device__ float g_lcc[NPTS * 10];   // (pt, k, xy)
__device__ float g_lf [NPTS * 64];   // local_feats

// out layout: [cls 32768*128 | topo 32768*128 | angle 32768 | axes 32768*2]
#define OFF_TOPO 4194304
#define OFF_ANG  8388608
#define OFF_AX   8421376

// ---------------- Kernel A: KNN (reference-bit-exact dist) + slaev2 eigh + lcc ----------------
__global__ __launch_bounds__(128)
void knn_geom_kernel(const float* __restrict__ xg, float* __restrict__ out)
{
    __shared__ float2 sp[NN];
    __shared__ float  ssq[NN];
    const int b = blockIdx.y;
    const float2* xb = reinterpret_cast<const float2*>(xg) + (size_t)b * NN;
    for (int i = threadIdx.x; i < NN; i += 128) {
        float2 v = xb[i];
        sp[i] = v;
        // sq = fl(x*x) + fl(y*y)  (jnp.sum(x*x, -1), no fma)
        ssq[i] = __fadd_rn(__fmul_rn(v.x, v.x), __fmul_rn(v.y, v.y));
    }
    __syncthreads();

    const int n = blockIdx.x * 128 + threadIdx.x;
    const float qx = sp[n].x, qy = sp[n].y;
    const float sqn = ssq[n];

    float d0 = 3.4e38f, d1 = 3.4e38f, d2 = 3.4e38f, d3 = 3.4e38f, d4 = 3.4e38f;
    int   i0 = 0, i1 = 0, i2 = 0, i3 = 0, i4 = 0;

    #pragma unroll 4
    for (int m = 0; m < NN; ++m) {
        float2 p = sp[m];
        // Eigen gemm k=2 fold: dot = fma(y*y', rn(x*x'))
        float dot = __fmaf_rn(p.y, qy, __fmul_rn(p.x, qx));
        // dist = rn( rn(sq_n + sq_m) - 2*dot )
        float dd = __fsub_rn(__fadd_rn(sqn, ssq[m]), __fmul_rn(2.0f, dot));
        if (dd < d4) {                      // strict <: lax.top_k stable tie-break by index
            if (dd < d3) {
                d4 = d3; i4 = i3;
                if (dd < d2) {
                    d3 = d2; i3 = i2;
                    if (dd < d1) {
                        d2 = d1; i2 = i1;
                        if (dd < d0) { d1 = d0; i1 = i0; d0 = dd; i0 = m; }
                        else          { d1 = dd; i1 = m; }
                    } else { d2 = dd; i2 = m; }
                } else { d3 = dd; i3 = m; }
            } else { d4 = dd; i4 = m; }
        }
    }

    int nb[5] = {i0, i1, i2, i3, i4};
    float rx[5], ry[5];
    #pragma unroll
    for (int k = 0; k < 5; ++k) {
        float2 p = sp[nb[k]];
        rx[k] = __fsub_rn(p.x, qx);
        ry[k] = __fsub_rn(p.y, qy);
    }
    // mean over k: sequential left-fold, then /5 (NOT *0.2)
    float sxs = __fadd_rn(__fadd_rn(__fadd_rn(__fadd_rn(rx[0], rx[1]), rx[2]), rx[3]), rx[4]);
    float sys = __fadd_rn(__fadd_rn(__fadd_rn(__fadd_rn(ry[0], ry[1]), ry[2]), ry[3]), ry[4]);
    float mx = __fdiv_rn(sxs, 5.0f);
    float my = __fdiv_rn(sys, 5.0f);
    float cx[5], cy[5];
    float sxx = 0.f, sxy = 0.f, syy = 0.f;
    #pragma unroll
    for (int k = 0; k < 5; ++k) {
        cx[k] = __fsub_rn(rx[k], mx);
        cy[k] = __fsub_rn(ry[k], my);
        sxx = __fmaf_rn(cx[k], cx[k], sxx);
        sxy = __fmaf_rn(cx[k], cy[k], sxy);
        syy = __fmaf_rn(cy[k], cy[k], syy);
    }
    float a  = __fadd_rn(__fmul_rn(sxx, 0.25f), 1e-6f);   // cov/(K-1) + EPS*I
    float bv = __fmul_rn(sxy, 0.25f);
    float c  = __fadd_rn(__fmul_rn(syy, 0.25f), 1e-6f);

    // ---- LAPACK slaev2 (a,c > 0 => sm > 0 => sgn1 = +1) ----
    float smv = a + c, df = a - c;
    float adf = fabsf(df);
    float tb  = bv + bv;
    float ab  = fabsf(tb);
    float rt;
    if (adf > ab)      { float t = ab / adf; rt = adf * sqrtf(1.f + t*t); }
    else if (adf < ab) { float t = adf / ab; rt = ab * sqrtf(1.f + t*t); }
    else               { rt = ab * 1.4142135623730951f; }
    float rt1 = 0.5f * (smv + rt);
    float acmx, acmn;
    if (fabsf(a) > fabsf(c)) { acmx = a; acmn = c; } else { acmx = c; acmn = a; }
    float rt2 = (acmx / rt1) * acmn - (bv / rt1) * bv;
    float cs; int sgn2;
    if (df >= 0.f) { cs = df + rt; sgn2 = 1; }
    else           { cs = df - rt; sgn2 = -1; }
    float acs = fabsf(cs), cs1, sn1;
    if (acs > ab)       { float ct = -tb / cs; sn1 = 1.f / sqrtf(1.f + ct*ct); cs1 = ct * sn1; }
    else if (ab == 0.f) { cs1 = 1.f; sn1 = 0.f; }
    else                { float tn = -cs / tb; cs1 = 1.f / sqrtf(1.f + tn*tn); sn1 = tn * cs1; }
    if (sgn2 == 1)      { float t = cs1; cs1 = -sn1; sn1 = t; }   // sgn1 == sgn2 swap

    // ssteqr ascending sort with column swap: cols = [v(e0), v(e1)]
    float e0, e1, v00, v10, v01, v11;
    if (rt2 < rt1) { e0 = rt2; e1 = rt1; v00 = -sn1; v10 = cs1; v01 = cs1;  v11 = sn1; }
    else           { e0 = rt1; e1 = rt2; v00 = cs1;  v10 = sn1; v01 = -sn1; v11 = cs1; }

    const int pt = b * NN + n;
    out[OFF_ANG + pt] = atan2f(v11, v01);
    float sL = sqrtf(fmaxf(e1, 1e-6f));
    float sS = sqrtf(fmaxf(e0, 1e-6f));
    float den = fmaxf(sL, sS) + 1e-6f;
    out[OFF_AX + pt * 2 + 0] = fmaxf(sL / den, 0.2f);
    out[OFF_AX + pt * 2 + 1] = fmaxf(sS / den, 0.2f);

    float* lp = g_lcc + (size_t)pt * 10;
    #pragma unroll
    for (int k = 0; k < 5; ++k) {
        lp[2*k]   = __fmaf_rn(cy[k], v10, __fmul_rn(cx[k], v00));
        lp[2*k+1] = __fmaf_rn(cy[k], v11, __fmul_rn(cx[k], v01));
    }
}

// ---------------- Kernel B: local MLP 2->64->128->64 + max over K ----------------
// 32 points/CTA (160 k-rows), 256 threads, all weights + activations in smem.
#define B_SMEM_FLOATS (128 + 64 + 8192 + 128 + 8192 + 64 + 320 + 64*161 + 160*129)
__global__ __launch_bounds__(256)
void local_mlp_kernel(const float* __restrict__ lw1, const float* __restrict__ lb1,
                      const float* __restrict__ lw2, const float* __restrict__ lb2,
                      const float* __restrict__ lw3, const float* __restrict__ lb3)
{
    extern __shared__ float smf[];
    float* w1s  = smf;             // 128
    float* b1s  = w1s + 128;       // 64
    float* w2s  = b1s + 64;        // 8192
    float* b2s  = w2s + 8192;      // 128
    float* w3s  = b2s + 128;       // 8192
    float* b3s  = w3s + 8192;      // 64
    float* lccs = b3s + 64;        // 320
    float* h1T  = lccs + 320;      // 64 x 161 (k-major, pad)
    float* h2s  = h1T + 64*161;    // 160 x 129

    const int tid  = threadIdx.x;
    const int base = blockIdx.x * 32;

    for (int i = tid; i < 128;  i += 256) { w1s[i] = lw1[i]; b2s[i] = lb2[i]; }
    for (int i = tid; i < 64;   i += 256) { b1s[i] = lb1[i]; b3s[i] = lb3[i]; }
    for (int i = tid; i < 8192; i += 256) { w2s[i] = lw2[i]; w3s[i] = lw3[i]; }
    for (int i = tid; i < 320;  i += 256) lccs[i] = g_lcc[(size_t)base * 10 + i];
    __syncthreads();

    // stage 1: h1 (160x64) -> transposed h1T[c*161 + r]
    for (int idx = tid; idx < 160 * 64; idx += 256) {
        int r = idx >> 6, c = idx & 63;
        float v = fmaf(lccs[2*r], w1s[c], fmaf(lccs[2*r+1], w1s[64 + c], b1s[c]));
        h1T[c * 161 + r] = fmaxf(v, 0.f);
    }
    __syncthreads();

    const int p  = tid >> 3;     // point 0..31
    const int cg = tid & 7;      // column group 0..7
    const int r0 = p * 5;

    // stage 2: h2 (160x128) = relu(h1 @ w2 + b2); tile 5 rows x 16 strided cols
    float acc[5][16];
    #pragma unroll
    for (int i = 0; i < 16; ++i) {
        float bvv = b2s[cg + 8*i];
        #pragma unroll
        for (int j = 0; j < 5; ++j) acc[j][i] = bvv;
    }
    for (int k = 0; k < 64; ++k) {
        float av[5];
        #pragma unroll
        for (int j = 0; j < 5; ++j) av[j] = h1T[k * 161 + r0 + j];
        float wv[16];
        #pragma unroll
        for (int i = 0; i < 16; ++i) wv[i] = w2s[k * 128 + cg + 8*i];
        #pragma unroll
        for (int j = 0; j < 5; ++j)
            #pragma unroll
            for (int i = 0; i < 16; ++i)
                acc[j][i] = fmaf(av[j], wv[i], acc[j][i]);
    }
    #pragma unroll
    for (int j = 0; j < 5; ++j)
        #pragma unroll
        for (int i = 0; i < 16; ++i)
            h2s[(r0 + j) * 129 + cg + 8*i] = fmaxf(acc[j][i], 0.f);
    __syncthreads();

    // stage 3: h3 (160x64) = relu(h2 @ w3 + b3), fused max over K (thread-local)
    float acc3[5][8];
    #pragma unroll
    for (int i = 0; i < 8; ++i) {
        float bvv = b3s[cg + 8*i];
        #pragma unroll
        for (int j = 0; j < 5; ++j) acc3[j][i] = bvv;
    }
    for (int k = 0; k < 128; ++k) {
        float av[5];
        #pragma unroll
        for (int j = 0; j < 5; ++j) av[j] = h2s[(r0 + j) * 129 + k];
        float wv[8];
        #pragma unroll
        for (int i = 0; i < 8; ++i) wv[i] = w3s[k * 64 + cg + 8*i];
        #pragma unroll
        for (int j = 0; j < 5; ++j)
            #pragma unroll
            for (int i = 0; i < 8; ++i)
                acc3[j][i] = fmaf(av[j], wv[i], acc3[j][i]);
    }
    #pragma unroll
    for (int i = 0; i < 8; ++i) {
        float m = 0.f;   // max(relu(.)) == relu floor 0
        #pragma unroll
        for (int j = 0; j < 5; ++j) m = fmaxf(m, acc3[j][i]);
        g_lf[(size_t)(base + p) * 64 + cg + 8*i] = m;
    }
}

// ---------------- Kernel C/D: heads  in -> 128 relu -> 128 relu ----------------
template<int INDIM, int INSTRIDE, bool USEX>
__global__ __launch_bounds__(256)
void head_kernel(const float* __restrict__ xg,
                 const float* __restrict__ w1, const float* __restrict__ b1,
                 const float* __restrict__ w2, const float* __restrict__ b2,
                 float* __restrict__ outp)
{
    extern __shared__ float smf[];
    float* w1s = smf;                   // INDIM*128
    float* b1s = w1s + INDIM * 128;     // 128
    float* w2s = b1s + 128;             // 16384
    float* b2s = w2s + 16384;           // 128
    float* ins = b2s + 128;             // 32 * INSTRIDE
    float* hs  = ins + 32 * INSTRIDE;   // 32 * 129

    const int tid  = threadIdx.x;
    const int base = blockIdx.x * 32;

    for (int i = tid; i < INDIM * 128; i += 256) w1s[i] = w1[i];
    for (int i = tid; i < 16384;       i += 256) w2s[i] = w2[i];
    for (int i = tid; i < 128;         i += 256) { b1s[i] = b1[i]; b2s[i] = b2[i]; }
    const int xoff = USEX ? 2 : 0;
    for (int idx = tid; idx < 32 * 64; idx += 256) {
        int p = idx >> 6, c = idx & 63;
        ins[p * INSTRIDE + xoff + c] = g_lf[(size_t)(base + p) * 64 + c];
    }
    if (USEX) {
        for (int idx = tid; idx < 64; idx += 256) {
            int p = idx >> 1, c = idx & 1;
            ins[p * INSTRIDE + c] = xg[(size_t)(base + p) * 2 + c];
        }
    }
    __syncthreads();

    const int p  = tid >> 3;
    const int cg = tid & 7;

    float acc[16];
    #pragma unroll
    for (int i = 0; i < 16; ++i) acc[i] = b1s[cg + 8*i];
    for (int k = 0; k < INDIM; ++k) {
        float a = ins[p * INSTRIDE + k];
        #pragma unroll
        for (int i = 0; i < 16; ++i)
            acc[i] = fmaf(a, w1s[k * 128 + cg + 8*i], acc[i]);
    }
    #pragma unroll
    for (int i = 0; i < 16; ++i) hs[p * 129 + cg + 8*i] = fmaxf(acc[i], 0.f);
    __syncthreads();

    float acc2[16];
    #pragma unroll
    for (int i = 0; i < 16; ++i) acc2[i] = b2s[cg + 8*i];
    for (int k = 0; k < 128; ++k) {
        float a = hs[p * 129 + k];
        #pragma unroll
        for (int i = 0; i < 16; ++i)
            acc2[i] = fmaf(a, w2s[k * 128 + cg + 8*i], acc2[i]);
    }
    float* op = outp + (size_t)(base + p) * 128;
    #pragma unroll
    for (int i = 0; i < 16; ++i) op[cg + 8*i] = fmaxf(acc2[i], 0.f);
}

// ---------------- launch ----------------
extern "C" void kernel_launch(void* const* d_in, const int* in_sizes, int n_in,
                              void* d_out, int out_size)
{
    (void)in_sizes; (void)n_in; (void)out_size;
    const float* x   = (const float*)d_in[0];
    const float* lw1 = (const float*)d_in[1];
    const float* lb1 = (const float*)d_in[2];
    const float* lw2 = (const float*)d_in[3];
    const float* lb2 = (const float*)d_in[4];
    const float* lw3 = (const float*)d_in[5];
    const float* lb3 = (const float*)d_in[6];
    const float* cw1 = (const float*)d_in[7];
    const float* cb1 = (const float*)d_in[8];
    const float* cw2 = (const float*)d_in[9];
    const float* cb2 = (const float*)d_in[10];
    const float* tw1 = (const float*)d_in[11];
    const float* tb1 = (const float*)d_in[12];
    const float* tw2 = (const float*)d_in[13];
    const float* tb2 = (const float*)d_in[14];
    float* out = (float*)d_out;

    const int smB = B_SMEM_FLOATS * 4;
    const int smC = (66*128 + 128 + 16384 + 128 + 32*69 + 32*129) * 4;
    const int smT = (64*128 + 128 + 16384 + 128 + 32*67 + 32*129) * 4;
    cudaFuncSetAttribute(local_mlp_kernel, cudaFuncAttributeMaxDynamicSharedMemorySize, smB);
    cudaFuncSetAttribute(head_kernel<66, 69, true>,  cudaFuncAttributeMaxDynamicSharedMemorySize, smC);
    cudaFuncSetAttribute(head_kernel<64, 67, false>, cudaFuncAttributeMaxDynamicSharedMemorySize, smT);

    knn_geom_kernel<<<dim3(NN/128, 8), 128>>>(x, out);
    local_mlp_kernel<<<NPTS/32, 256, smB>>>(lw1, lb1, lw2, lb2, lw3, lb3);
    head_kernel<66, 69, true ><<<NPTS/32, 256, smC>>>(x, cw1, cb1, cw2, cb2, out);
    head_kernel<64, 67, false><<<NPTS/32, 256, smT>>>(x, tw1, tb1, tw2, tb2, out + OFF_TOPO);
}